// round 1
// baseline (speedup 1.0000x reference)
#include <cuda_runtime.h>
#include <math.h>

// ---------------------------------------------------------------------------
// SelectiveSSM (Mamba-style block)
//   B=2, L=2048, d_model=1024, d_inner=2048, d_state=16, d_conv=4
// Pipeline:
//   1) xz    = x @ W_in^T                      GEMM  (4096 x 4096 x 1024)
//   2) xconv = silu(causal_dwconv(xz[:, :2048]))
//   3) xdbl  = xconv @ W_x^T                   GEMM  (4096 x 2080 x 2048)
//   4) delta = softplus(xdbl[:, :2048] @ W_dt^T + b_dt)  GEMM (4096x2048x2048)
//   5) chunked selective scan (3 passes) + y*silu(z) gating
//   6) out   = yg @ W_out^T                    GEMM  (4096 x 1024 x 2048)
// ---------------------------------------------------------------------------

#define BATCH  2
#define SEQ    2048
#define DM     1024
#define DI     2048
#define DS     16
#define DC     4
#define DXL    (DI + 2*DS)      // 2080
#define CHUNK  128
#define NCH    (SEQ / CHUNK)    // 16
#define MTOT   (BATCH * SEQ)    // 4096

// ------------------------- scratch (static, no mallocs) -------------------
__device__ float g_xz   [(size_t)MTOT * 2 * DI];   // 64 MB
__device__ float g_xconv[(size_t)MTOT * DI];       // 32 MB
__device__ float g_xdbl [(size_t)MTOT * DXL];      // 32.5 MB
__device__ float g_delta[(size_t)MTOT * DI];       // 32 MB
__device__ float g_yg   [(size_t)MTOT * DI];       // 32 MB
__device__ float g_chA  [(size_t)BATCH * NCH * DI * DS];  // 4 MB
__device__ float g_chH  [(size_t)BATCH * NCH * DI * DS];  // 4 MB
__device__ float g_hInit[(size_t)BATCH * NCH * DI * DS];  // 4 MB

// ---------------------------------------------------------------------------
// SGEMM:  C[M,N] = A[M,K(lda)] * W[N,K]^T     (W row-major [N,K])
// 128x128 tile, BK=8, 256 threads, 8x8 per thread microtile.
// MODE 0: plain store.  MODE 1: softplus(acc + bias[n]).
// Requires: M % 128 == 0, K % 8 == 0, N % 4 == 0 (N may be non-mult of 128).
// ---------------------------------------------------------------------------
template<int MODE>
__global__ void __launch_bounds__(256, 2) sgemm_tn(
    const float* __restrict__ A, int lda,
    const float* __restrict__ W,
    const float* __restrict__ bias,
    float* __restrict__ C, int ldc,
    int M, int N, int K)
{
    const int BM = 128, BN = 128, BK = 8;
    __shared__ float As[BK][BM];
    __shared__ float Bs[BK][BN];

    const int tid = threadIdx.x;
    const int tx  = tid & 15;        // 0..15  (n direction)
    const int ty  = tid >> 4;        // 0..15  (m direction)
    const int m0  = blockIdx.y * BM;
    const int n0  = blockIdx.x * BN;

    const int loadRow = tid >> 1;        // 0..127
    const int loadCol = (tid & 1) << 2;  // 0 or 4

    float acc[8][8];
#pragma unroll
    for (int i = 0; i < 8; i++)
#pragma unroll
        for (int j = 0; j < 8; j++) acc[i][j] = 0.f;

    const float* Aptr = A + (size_t)(m0 + loadRow) * lda + loadCol;
    const bool   wValid = (n0 + loadRow) < N;
    const float* Wptr = W + (size_t)(n0 + loadRow) * K + loadCol;

    for (int k0 = 0; k0 < K; k0 += BK) {
        float4 av = *(const float4*)(Aptr + k0);
        float4 wv = wValid ? *(const float4*)(Wptr + k0)
                           : make_float4(0.f, 0.f, 0.f, 0.f);
        As[loadCol + 0][loadRow] = av.x;
        As[loadCol + 1][loadRow] = av.y;
        As[loadCol + 2][loadRow] = av.z;
        As[loadCol + 3][loadRow] = av.w;
        Bs[loadCol + 0][loadRow] = wv.x;
        Bs[loadCol + 1][loadRow] = wv.y;
        Bs[loadCol + 2][loadRow] = wv.z;
        Bs[loadCol + 3][loadRow] = wv.w;
        __syncthreads();

#pragma unroll
        for (int k = 0; k < BK; k++) {
            float a[8], b[8];
            *(float4*)&a[0] = *(const float4*)&As[k][ty * 4];
            *(float4*)&a[4] = *(const float4*)&As[k][64 + ty * 4];
            *(float4*)&b[0] = *(const float4*)&Bs[k][tx * 4];
            *(float4*)&b[4] = *(const float4*)&Bs[k][64 + tx * 4];
#pragma unroll
            for (int i = 0; i < 8; i++)
#pragma unroll
                for (int j = 0; j < 8; j++)
                    acc[i][j] += a[i] * b[j];
        }
        __syncthreads();
    }

    // epilogue + store
#pragma unroll
    for (int i = 0; i < 8; i++) {
        const int m = m0 + ((i < 4) ? (ty * 4 + i) : (64 + ty * 4 + (i - 4)));
#pragma unroll
        for (int jj = 0; jj < 2; jj++) {
            const int n = n0 + ((jj == 0) ? (tx * 4) : (64 + tx * 4));
            if (n + 3 < N || n < N) {           // N % 4 == 0 -> whole float4 in or out
                if (n >= N) continue;
                float v[4];
#pragma unroll
                for (int t = 0; t < 4; t++) {
                    float val = acc[i][jj * 4 + t];
                    if (MODE == 1) {
                        val += bias[n + t];
                        val = (val > 20.f) ? val : log1pf(expf(val));
                    }
                    v[t] = val;
                }
                *(float4*)&C[(size_t)m * ldc + n] = *(float4*)v;
            }
        }
    }
}

// ---------------------------------------------------------------------------
// Depthwise causal conv (K=4) over xz[:, :, :DI], then SiLU.
// ---------------------------------------------------------------------------
__global__ void conv_silu_kernel(const float* __restrict__ xz,
                                 const float* __restrict__ w,
                                 const float* __restrict__ bconv,
                                 float* __restrict__ xconv)
{
    const int idx = blockIdx.x * blockDim.x + threadIdx.x;   // over MTOT*DI
    if (idx >= MTOT * DI) return;
    const int d  = idx & (DI - 1);
    const int ml = idx >> 11;            // DI = 2048 = 2^11
    const int l  = ml & (SEQ - 1);

    float acc = bconv[d];
#pragma unroll
    for (int k = 0; k < DC; k++) {
        const int lt = l - (DC - 1) + k;
        if (lt >= 0)
            acc += xz[(size_t)(ml - (DC - 1) + k) * (2 * DI) + d] * w[d * DC + k];
    }
    const float sg = 1.f / (1.f + expf(-acc));
    xconv[idx] = acc * sg;
}

// ---------------------------------------------------------------------------
// Scan pass A: per (b, chunk, d) compute chunk decay-product and local state.
// ---------------------------------------------------------------------------
__global__ void __launch_bounds__(256) scan_passA(
    const float* __restrict__ xconv, const float* __restrict__ delta,
    const float* __restrict__ xdbl,  const float* __restrict__ A_log,
    float* __restrict__ chA, float* __restrict__ chH)
{
    __shared__ float Bsm[CHUNK][DS];
    const int d = blockIdx.x * blockDim.x + threadIdx.x;
    const int c = blockIdx.y, b = blockIdx.z;

    for (int i = threadIdx.x; i < CHUNK * DS; i += blockDim.x) {
        const int t = i >> 4, s = i & 15;
        Bsm[t][s] = xdbl[(size_t)(b * SEQ + c * CHUNK + t) * DXL + DI + s];
    }
    __syncthreads();

    float Aa[DS], st[DS], cum[DS];
#pragma unroll
    for (int s = 0; s < DS; s++) {
        Aa[s]  = -expf(A_log[d * DS + s]);
        st[s]  = 0.f;
        cum[s] = 1.f;
    }
    const size_t base = (size_t)(b * SEQ + c * CHUNK) * DI + d;
    for (int t = 0; t < CHUNK; t++) {
        const float dt = delta[base + (size_t)t * DI];
        const float xv = xconv[base + (size_t)t * DI];
#pragma unroll
        for (int s = 0; s < DS; s++) {
            const float dec = __expf(dt * Aa[s]);
            cum[s] *= dec;
            st[s]   = dec * st[s] + Bsm[t][s] * xv;
        }
    }
    const size_t o = ((size_t)(b * NCH + c) * DI + d) * DS;
#pragma unroll
    for (int s = 0; s < DS; s++) { chA[o + s] = cum[s]; chH[o + s] = st[s]; }
}

// ---------------------------------------------------------------------------
// Scan pass B: sequential prefix over the 16 chunks (per b,d).
// ---------------------------------------------------------------------------
__global__ void scan_passB(const float* __restrict__ chA,
                           const float* __restrict__ chH,
                           float* __restrict__ hInit)
{
    const int idx = blockIdx.x * blockDim.x + threadIdx.x;  // b*DI + d
    if (idx >= BATCH * DI) return;
    const int b = idx / DI, d = idx % DI;
    float h[DS];
#pragma unroll
    for (int s = 0; s < DS; s++) h[s] = 0.f;
    for (int c = 0; c < NCH; c++) {
        const size_t o = ((size_t)(b * NCH + c) * DI + d) * DS;
#pragma unroll
        for (int s = 0; s < DS; s++) hInit[o + s] = h[s];
#pragma unroll
        for (int s = 0; s < DS; s++) h[s] = chA[o + s] * h[s] + chH[o + s];
    }
}

// ---------------------------------------------------------------------------
// Scan pass C: replay chunks from prefix state; fuse C-contraction, D-skip,
// and y * silu(z) gating.
// ---------------------------------------------------------------------------
__global__ void __launch_bounds__(256) scan_passC(
    const float* __restrict__ xconv, const float* __restrict__ delta,
    const float* __restrict__ xdbl,  const float* __restrict__ A_log,
    const float* __restrict__ Dv,    const float* __restrict__ xz,
    const float* __restrict__ hInit, float* __restrict__ yg)
{
    __shared__ float Bsm[CHUNK][DS];
    __shared__ float Csm[CHUNK][DS];
    const int d = blockIdx.x * blockDim.x + threadIdx.x;
    const int c = blockIdx.y, b = blockIdx.z;

    for (int i = threadIdx.x; i < CHUNK * DS; i += blockDim.x) {
        const int t = i >> 4, s = i & 15;
        const size_t row = (size_t)(b * SEQ + c * CHUNK + t) * DXL;
        Bsm[t][s] = xdbl[row + DI + s];
        Csm[t][s] = xdbl[row + DI + DS + s];
    }
    __syncthreads();

    float Aa[DS], st[DS];
    const size_t o = ((size_t)(b * NCH + c) * DI + d) * DS;
#pragma unroll
    for (int s = 0; s < DS; s++) {
        Aa[s] = -expf(A_log[d * DS + s]);
        st[s] = hInit[o + s];
    }
    const float Dd = Dv[d];
    const size_t base = (size_t)(b * SEQ + c * CHUNK) * DI + d;
    for (int t = 0; t < CHUNK; t++) {
        const float dt = delta[base + (size_t)t * DI];
        const float xv = xconv[base + (size_t)t * DI];
        float y = 0.f;
#pragma unroll
        for (int s = 0; s < DS; s++) {
            const float dec = __expf(dt * Aa[s]);
            st[s] = dec * st[s] + Bsm[t][s] * xv;
            y += st[s] * Csm[t][s];
        }
        y += Dd * xv;
        const float z = xz[(size_t)(b * SEQ + c * CHUNK + t) * (2 * DI) + DI + d];
        const float sg = 1.f / (1.f + expf(-z));
        yg[base + (size_t)t * DI] = y * (z * sg);
    }
}

// ---------------------------------------------------------------------------
extern "C" void kernel_launch(void* const* d_in, const int* in_sizes, int n_in,
                              void* d_out, int out_size)
{
    const float* x      = (const float*)d_in[0];
    const float* W_in   = (const float*)d_in[1];
    const float* w_conv = (const float*)d_in[2];
    const float* b_conv = (const float*)d_in[3];
    const float* W_x    = (const float*)d_in[4];
    const float* W_dt   = (const float*)d_in[5];
    const float* b_dt   = (const float*)d_in[6];
    const float* A_log  = (const float*)d_in[7];
    const float* Dv     = (const float*)d_in[8];
    const float* W_out  = (const float*)d_in[9];
    float* out = (float*)d_out;

    float *xz, *xconv, *xdbl, *delta, *yg, *chA, *chH, *hInit;
    cudaGetSymbolAddress((void**)&xz,    g_xz);
    cudaGetSymbolAddress((void**)&xconv, g_xconv);
    cudaGetSymbolAddress((void**)&xdbl,  g_xdbl);
    cudaGetSymbolAddress((void**)&delta, g_delta);
    cudaGetSymbolAddress((void**)&yg,    g_yg);
    cudaGetSymbolAddress((void**)&chA,   g_chA);
    cudaGetSymbolAddress((void**)&chH,   g_chH);
    cudaGetSymbolAddress((void**)&hInit, g_hInit);

    // 1) xz = x @ W_in^T          (M=4096, N=4096, K=1024)
    {
        dim3 grid((2 * DI + 127) / 128, MTOT / 128);
        sgemm_tn<0><<<grid, 256>>>(x, DM, W_in, nullptr, xz, 2 * DI,
                                   MTOT, 2 * DI, DM);
    }
    // 2) depthwise causal conv + silu
    {
        int n = MTOT * DI;
        conv_silu_kernel<<<(n + 255) / 256, 256>>>(xz, w_conv, b_conv, xconv);
    }
    // 3) xdbl = xconv @ W_x^T     (M=4096, N=2080, K=2048)
    {
        dim3 grid((DXL + 127) / 128, MTOT / 128);
        sgemm_tn<0><<<grid, 256>>>(xconv, DI, W_x, nullptr, xdbl, DXL,
                                   MTOT, DXL, DI);
    }
    // 4) delta = softplus(xdbl[:, :DI] @ W_dt^T + b_dt)   (4096 x 2048 x 2048)
    {
        dim3 grid((DI + 127) / 128, MTOT / 128);
        sgemm_tn<1><<<grid, 256>>>(xdbl, DXL, W_dt, b_dt, delta, DI,
                                   MTOT, DI, DI);
    }
    // 5) chunked selective scan
    {
        dim3 gridA(DI / 256, NCH, BATCH);
        scan_passA<<<gridA, 256>>>(xconv, delta, xdbl, A_log, chA, chH);
        scan_passB<<<(BATCH * DI + 255) / 256, 256>>>(chA, chH, hInit);
        scan_passC<<<gridA, 256>>>(xconv, delta, xdbl, A_log, Dv, xz,
                                   hInit, yg);
    }
    // 6) out = yg @ W_out^T       (M=4096, N=1024, K=2048)
    {
        dim3 grid((DM + 127) / 128, MTOT / 128);
        sgemm_tn<0><<<grid, 256>>>(yg, DI, W_out, nullptr, out, DM,
                                   MTOT, DM, DI);
    }
}

// round 3
// speedup vs baseline: 1.9025x; 1.9025x over previous
#include <cuda_runtime.h>
#include <cuda_bf16.h>
#include <cstdint>
#include <math.h>

// ---------------------------------------------------------------------------
// SelectiveSSM (Mamba-style block) — split-bf16 mma.sync (HMMA) GEMMs
//   B=2, L=2048, d_model=1024, d_inner=2048, d_state=16, d_conv=4
// NOTE: harness ptxas target is sm_103 (no 'a'), so tcgen05 is unavailable;
// mma.sync.m16n8k16 bf16 is the fastest available tensor path.
// ---------------------------------------------------------------------------

#define BATCH  2
#define SEQ    2048
#define DM     1024
#define DI     2048
#define DS     16
#define DC     4
#define DXL    (DI + 2*DS)      // 2080
#define CHUNK  128
#define NCH    (SEQ / CHUNK)    // 16
#define MTOT   (BATCH * SEQ)    // 4096

// ------------------------- scratch (static, no mallocs) -------------------
__device__ float g_xz   [(size_t)MTOT * 2 * DI];
__device__ float g_xconv[(size_t)MTOT * DI];
__device__ float g_xdbl [(size_t)MTOT * DXL];
__device__ float g_delta[(size_t)MTOT * DI];
__device__ float g_yg   [(size_t)MTOT * DI];
__device__ float g_chA  [(size_t)BATCH * NCH * DI * DS];
__device__ float g_chH  [(size_t)BATCH * NCH * DI * DS];
__device__ float g_hInit[(size_t)BATCH * NCH * DI * DS];

// ======================= helpers ===========================================
__device__ __forceinline__ uint32_t smem_u32(const void* p) {
    uint32_t a;
    asm("{ .reg .u64 t; cvta.to.shared.u64 t, %1; cvt.u32.u64 %0, t; }"
        : "=r"(a) : "l"(p));
    return a;
}

__device__ __forceinline__ uint32_t swz(uint32_t off) {     // SW128 swizzle
    return off ^ ((off >> 3) & 0x70);
}

__device__ __forceinline__ void ldsm4(uint32_t* r, uint32_t addr) {
    asm volatile("ldmatrix.sync.aligned.m8n8.x4.shared.b16 {%0,%1,%2,%3}, [%4];"
        : "=r"(r[0]), "=r"(r[1]), "=r"(r[2]), "=r"(r[3]) : "r"(addr));
}

__device__ __forceinline__ void mma16816(float* c, const uint32_t* a,
                                         const uint32_t* b) {
    asm volatile(
        "mma.sync.aligned.m16n8k16.row.col.f32.bf16.bf16.f32 "
        "{%0,%1,%2,%3}, {%4,%5,%6,%7}, {%8,%9}, {%0,%1,%2,%3};"
        : "+f"(c[0]), "+f"(c[1]), "+f"(c[2]), "+f"(c[3])
        : "r"(a[0]), "r"(a[1]), "r"(a[2]), "r"(a[3]),
          "r"(b[0]), "r"(b[1]));
}

// ===========================================================================
// split-bf16 GEMM:  C[M,N] = A[M,K] * W[N,K]^T  (fp32 in/out)
// CTA: 128x128 tile, 8 warps (2x4), warp tile 64x32, K-chunk 64,
// double-buffered SMEM (Ahi,Alo,Whi,Wlo per stage; SW128 swizzled 128B rows).
// MODE 0: plain store.  MODE 1: softplus(acc + bias[n]).
// Requires M % 128 == 0, K % 64 == 0, N % 8 == 0.
// ===========================================================================

#define TILE_B   16384            // 128 rows x 128 bytes (64 bf16)
#define STAGE_B  (4 * TILE_B)     // Ahi, Alo, Whi, Wlo
#define GEMM_SMEM (2 * STAGE_B)   // 131072

// Load a 128x64 fp32 tile, split to bf16 hi/lo, store SW128-swizzled.
__device__ __forceinline__ void load_convert_tile(
    const float* __restrict__ src, int ld, int row0, int rowsValid, int k0,
    char* __restrict__ hi, char* __restrict__ lo, int tid)
{
#pragma unroll
    for (int it = 0; it < 8; it++) {
        int i   = tid + it * 256;           // 0..2047
        int row = i >> 4;
        int c4  = i & 15;
        float4 v;
        if (row < rowsValid)
            v = *(const float4*)(src + (size_t)(row0 + row) * ld + k0 + c4 * 4);
        else
            v = make_float4(0.f, 0.f, 0.f, 0.f);

        float f[4] = {v.x, v.y, v.z, v.w};
        __nv_bfloat162 hp0, hp1, lp0, lp1;
        {
            __nv_bfloat16 h0 = __float2bfloat16(f[0]);
            __nv_bfloat16 h1 = __float2bfloat16(f[1]);
            __nv_bfloat16 h2 = __float2bfloat16(f[2]);
            __nv_bfloat16 h3 = __float2bfloat16(f[3]);
            hp0.x = h0; hp0.y = h1; hp1.x = h2; hp1.y = h3;
            lp0.x = __float2bfloat16(f[0] - __bfloat162float(h0));
            lp0.y = __float2bfloat16(f[1] - __bfloat162float(h1));
            lp1.x = __float2bfloat16(f[2] - __bfloat162float(h2));
            lp1.y = __float2bfloat16(f[3] - __bfloat162float(h3));
        }
        uint32_t b0 = (uint32_t)(row * 128 + c4 * 8);
        uint32_t s0 = swz(b0);
        uint32_t s1 = swz(b0 + 4);
        *(__nv_bfloat162*)(hi + s0) = hp0;
        *(__nv_bfloat162*)(hi + s1) = hp1;
        *(__nv_bfloat162*)(lo + s0) = lp0;
        *(__nv_bfloat162*)(lo + s1) = lp1;
    }
}

template<int MODE>
__global__ void __launch_bounds__(256, 1) hgemm_tn(
    const float* __restrict__ A, int lda,
    const float* __restrict__ W,
    const float* __restrict__ bias,
    float* __restrict__ C, int ldc,
    int M, int N, int K)
{
    extern __shared__ __align__(1024) char smem[];
    const uint32_t sb  = smem_u32(smem);
    const int tid  = threadIdx.x;
    const int wid  = tid >> 5;
    const int lane = tid & 31;
    const int wm   = wid >> 2;       // 0..1  (m)
    const int wn   = wid & 3;        // 0..3  (n)
    const int m0   = blockIdx.y * 128;
    const int n0   = blockIdx.x * 128;
    const int nValid = min(128, N - n0);

    // per-lane ldmatrix row/k-segment mapping
    const int g     = lane >> 3;                    // 8-lane group
    const int aRow  = (lane & 7) + ((g & 1) << 3);  // A: g0 r0-7 k0, g1 r8-15 k0,
    const int aKsg  = (g >> 1) << 3;                //    g2 r0-7 k8, g3 r8-15 k8
    const int bRow  = (lane & 7) + ((g >> 1) << 3); // B: g0 n0-7 k0, g1 n0-7 k8,
    const int bKsg  = (g & 1) << 3;                 //    g2 n8-15 k0, g3 n8-15 k8

    float Cf[4][4][4];
#pragma unroll
    for (int i = 0; i < 4; i++)
#pragma unroll
        for (int j = 0; j < 4; j++)
#pragma unroll
            for (int e = 0; e < 4; e++) Cf[i][j][e] = 0.f;

    char* stg[2] = { smem, smem + STAGE_B };
    const int NC = K >> 6;

    // preload chunk 0 -> stage 0
    load_convert_tile(A, lda, m0, 128,    0, stg[0] + 0*TILE_B, stg[0] + 1*TILE_B, tid);
    load_convert_tile(W, K,   n0, nValid, 0, stg[0] + 2*TILE_B, stg[0] + 3*TILE_B, tid);

    for (int c = 0; c < NC; c++) {
        __syncthreads();
        if (c + 1 < NC) {
            const int s2 = (c + 1) & 1;
            const int k0 = (c + 1) << 6;
            load_convert_tile(A, lda, m0, 128,    k0, stg[s2] + 0*TILE_B, stg[s2] + 1*TILE_B, tid);
            load_convert_tile(W, K,   n0, nValid, k0, stg[s2] + 2*TILE_B, stg[s2] + 3*TILE_B, tid);
        }
        const uint32_t base  = sb + (uint32_t)((c & 1) * STAGE_B);
        const uint32_t bAhi = base + 0 * TILE_B;
        const uint32_t bAlo = base + 1 * TILE_B;
        const uint32_t bWhi = base + 2 * TILE_B;
        const uint32_t bWlo = base + 3 * TILE_B;

#pragma unroll
        for (int ks = 0; ks < 4; ks++) {
            uint32_t ahi[4][4], alo[4][4], whi[2][4], wlo[2][4];
#pragma unroll
            for (int fm = 0; fm < 4; fm++) {
                uint32_t off = swz((uint32_t)((wm*64 + fm*16 + aRow) * 128
                                              + (ks*16 + aKsg) * 2));
                ldsm4(ahi[fm], bAhi + off);
                ldsm4(alo[fm], bAlo + off);
            }
#pragma unroll
            for (int h = 0; h < 2; h++) {
                uint32_t off = swz((uint32_t)((wn*32 + h*16 + bRow) * 128
                                              + (ks*16 + bKsg) * 2));
                ldsm4(whi[h], bWhi + off);
                ldsm4(wlo[h], bWlo + off);
            }
            // whi[h] regs: r0=(n0-7,k0-7) r1=(n0-7,k8-15) r2=(n8-15,k0-7) r3=(n8-15,k8-15)
#pragma unroll
            for (int fm = 0; fm < 4; fm++) {
#pragma unroll
                for (int fn = 0; fn < 4; fn++) {
                    const uint32_t* bh = &whi[fn >> 1][(fn & 1) * 2];
                    const uint32_t* bl = &wlo[fn >> 1][(fn & 1) * 2];
                    mma16816(Cf[fm][fn], ahi[fm], bh);
                    mma16816(Cf[fm][fn], ahi[fm], bl);
                    mma16816(Cf[fm][fn], alo[fm], bh);
                }
            }
        }
    }

    // epilogue: write C frags from registers
    const int mrow = m0 + wm * 64 + (lane >> 2);
    const int ncol = n0 + wn * 32 + (lane & 3) * 2;
#pragma unroll
    for (int fm = 0; fm < 4; fm++) {
#pragma unroll
        for (int fn = 0; fn < 4; fn++) {
#pragma unroll
            for (int half = 0; half < 2; half++) {
                const int m = mrow + fm * 16 + half * 8;
                const int n = ncol + fn * 8;
                if (n < N) {
                    float v0 = Cf[fm][fn][half * 2 + 0];
                    float v1 = Cf[fm][fn][half * 2 + 1];
                    if (MODE == 1) {
                        v0 += bias[n];
                        v1 += bias[n + 1];
                        v0 = (v0 > 20.f) ? v0 : log1pf(expf(v0));
                        v1 = (v1 > 20.f) ? v1 : log1pf(expf(v1));
                    }
                    *(float2*)&C[(size_t)m * ldc + n] = make_float2(v0, v1);
                }
            }
        }
    }
}

// ---------------------------------------------------------------------------
// Depthwise causal conv (K=4) over xz[:, :, :DI], then SiLU.
// ---------------------------------------------------------------------------
__global__ void conv_silu_kernel(const float* __restrict__ xz,
                                 const float* __restrict__ w,
                                 const float* __restrict__ bconv,
                                 float* __restrict__ xconv)
{
    const int idx = blockIdx.x * blockDim.x + threadIdx.x;
    if (idx >= MTOT * DI) return;
    const int d  = idx & (DI - 1);
    const int ml = idx >> 11;
    const int l  = ml & (SEQ - 1);

    float acc = bconv[d];
#pragma unroll
    for (int k = 0; k < DC; k++) {
        const int lt = l - (DC - 1) + k;
        if (lt >= 0)
            acc += xz[(size_t)(ml - (DC - 1) + k) * (2 * DI) + d] * w[d * DC + k];
    }
    const float sg = 1.f / (1.f + expf(-acc));
    xconv[idx] = acc * sg;
}

// ---------------------------------------------------------------------------
// Scan pass A: per (b, chunk, d) compute chunk decay-product and local state.
// ---------------------------------------------------------------------------
__global__ void __launch_bounds__(256) scan_passA(
    const float* __restrict__ xconv, const float* __restrict__ delta,
    const float* __restrict__ xdbl,  const float* __restrict__ A_log,
    float* __restrict__ chA, float* __restrict__ chH)
{
    __shared__ float Bsm[CHUNK][DS];
    const int d = blockIdx.x * blockDim.x + threadIdx.x;
    const int c = blockIdx.y, b = blockIdx.z;

    for (int i = threadIdx.x; i < CHUNK * DS; i += blockDim.x) {
        const int t = i >> 4, s = i & 15;
        Bsm[t][s] = xdbl[(size_t)(b * SEQ + c * CHUNK + t) * DXL + DI + s];
    }
    __syncthreads();

    float Aa[DS], st[DS], cum[DS];
#pragma unroll
    for (int s = 0; s < DS; s++) {
        Aa[s]  = -expf(A_log[d * DS + s]);
        st[s]  = 0.f;
        cum[s] = 1.f;
    }
    const size_t base = (size_t)(b * SEQ + c * CHUNK) * DI + d;
    for (int t = 0; t < CHUNK; t++) {
        const float dt = delta[base + (size_t)t * DI];
        const float xv = xconv[base + (size_t)t * DI];
#pragma unroll
        for (int s = 0; s < DS; s++) {
            const float dec = __expf(dt * Aa[s]);
            cum[s] *= dec;
            st[s]   = dec * st[s] + Bsm[t][s] * xv;
        }
    }
    const size_t o = ((size_t)(b * NCH + c) * DI + d) * DS;
#pragma unroll
    for (int s = 0; s < DS; s++) { chA[o + s] = cum[s]; chH[o + s] = st[s]; }
}

// ---------------------------------------------------------------------------
// Scan pass B: sequential prefix over the 16 chunks (per b,d).
// ---------------------------------------------------------------------------
__global__ void scan_passB(const float* __restrict__ chA,
                           const float* __restrict__ chH,
                           float* __restrict__ hInit)
{
    const int idx = blockIdx.x * blockDim.x + threadIdx.x;
    if (idx >= BATCH * DI) return;
    const int b = idx / DI, d = idx % DI;
    float h[DS];
#pragma unroll
    for (int s = 0; s < DS; s++) h[s] = 0.f;
    for (int c = 0; c < NCH; c++) {
        const size_t o = ((size_t)(b * NCH + c) * DI + d) * DS;
#pragma unroll
        for (int s = 0; s < DS; s++) hInit[o + s] = h[s];
#pragma unroll
        for (int s = 0; s < DS; s++) h[s] = chA[o + s] * h[s] + chH[o + s];
    }
}

// ---------------------------------------------------------------------------
// Scan pass C: replay chunks from prefix state; fuse C-contraction, D-skip,
// and y * silu(z) gating.
// ---------------------------------------------------------------------------
__global__ void __launch_bounds__(256) scan_passC(
    const float* __restrict__ xconv, const float* __restrict__ delta,
    const float* __restrict__ xdbl,  const float* __restrict__ A_log,
    const float* __restrict__ Dv,    const float* __restrict__ xz,
    const float* __restrict__ hInit, float* __restrict__ yg)
{
    __shared__ float Bsm[CHUNK][DS];
    __shared__ float Csm[CHUNK][DS];
    const int d = blockIdx.x * blockDim.x + threadIdx.x;
    const int c = blockIdx.y, b = blockIdx.z;

    for (int i = threadIdx.x; i < CHUNK * DS; i += blockDim.x) {
        const int t = i >> 4, s = i & 15;
        const size_t row = (size_t)(b * SEQ + c * CHUNK + t) * DXL;
        Bsm[t][s] = xdbl[row + DI + s];
        Csm[t][s] = xdbl[row + DI + DS + s];
    }
    __syncthreads();

    float Aa[DS], st[DS];
    const size_t o = ((size_t)(b * NCH + c) * DI + d) * DS;
#pragma unroll
    for (int s = 0; s < DS; s++) {
        Aa[s] = -expf(A_log[d * DS + s]);
        st[s] = hInit[o + s];
    }
    const float Dd = Dv[d];
    const size_t base = (size_t)(b * SEQ + c * CHUNK) * DI + d;
    for (int t = 0; t < CHUNK; t++) {
        const float dt = delta[base + (size_t)t * DI];
        const float xv = xconv[base + (size_t)t * DI];
        float y = 0.f;
#pragma unroll
        for (int s = 0; s < DS; s++) {
            const float dec = __expf(dt * Aa[s]);
            st[s] = dec * st[s] + Bsm[t][s] * xv;
            y += st[s] * Csm[t][s];
        }
        y += Dd * xv;
        const float z = xz[(size_t)(b * SEQ + c * CHUNK + t) * (2 * DI) + DI + d];
        const float sg = 1.f / (1.f + expf(-z));
        yg[base + (size_t)t * DI] = y * (z * sg);
    }
}

// ---------------------------------------------------------------------------
static void launch_hgemm(const float* A, int lda, const float* W,
                         const float* bias, float* C, int ldc,
                         int M, int N, int K, int mode)
{
    dim3 grid((N + 127) / 128, M / 128);
    if (mode == 0) {
        cudaFuncSetAttribute(hgemm_tn<0>,
            cudaFuncAttributeMaxDynamicSharedMemorySize, GEMM_SMEM);
        hgemm_tn<0><<<grid, 256, GEMM_SMEM>>>(A, lda, W, bias, C, ldc, M, N, K);
    } else {
        cudaFuncSetAttribute(hgemm_tn<1>,
            cudaFuncAttributeMaxDynamicSharedMemorySize, GEMM_SMEM);
        hgemm_tn<1><<<grid, 256, GEMM_SMEM>>>(A, lda, W, bias, C, ldc, M, N, K);
    }
}

extern "C" void kernel_launch(void* const* d_in, const int* in_sizes, int n_in,
                              void* d_out, int out_size)
{
    const float* x      = (const float*)d_in[0];
    const float* W_in   = (const float*)d_in[1];
    const float* w_conv = (const float*)d_in[2];
    const float* b_conv = (const float*)d_in[3];
    const float* W_x    = (const float*)d_in[4];
    const float* W_dt   = (const float*)d_in[5];
    const float* b_dt   = (const float*)d_in[6];
    const float* A_log  = (const float*)d_in[7];
    const float* Dv     = (const float*)d_in[8];
    const float* W_out  = (const float*)d_in[9];
    float* out = (float*)d_out;

    float *xz, *xconv, *xdbl, *delta, *yg, *chA, *chH, *hInit;
    cudaGetSymbolAddress((void**)&xz,    g_xz);
    cudaGetSymbolAddress((void**)&xconv, g_xconv);
    cudaGetSymbolAddress((void**)&xdbl,  g_xdbl);
    cudaGetSymbolAddress((void**)&delta, g_delta);
    cudaGetSymbolAddress((void**)&yg,    g_yg);
    cudaGetSymbolAddress((void**)&chA,   g_chA);
    cudaGetSymbolAddress((void**)&chH,   g_chH);
    cudaGetSymbolAddress((void**)&hInit, g_hInit);

    // 1) xz = x @ W_in^T          (M=4096, N=4096, K=1024)
    launch_hgemm(x, DM, W_in, nullptr, xz, 2 * DI, MTOT, 2 * DI, DM, 0);

    // 2) depthwise causal conv + silu
    {
        int n = MTOT * DI;
        conv_silu_kernel<<<(n + 255) / 256, 256>>>(xz, w_conv, b_conv, xconv);
    }

    // 3) xdbl = xconv @ W_x^T     (M=4096, N=2080, K=2048)
    launch_hgemm(xconv, DI, W_x, nullptr, xdbl, DXL, MTOT, DXL, DI, 0);

    // 4) delta = softplus(xdbl[:, :DI] @ W_dt^T + b_dt)
    launch_hgemm(xdbl, DXL, W_dt, b_dt, delta, DI, MTOT, DI, DI, 1);

    // 5) chunked selective scan
    {
        dim3 gridA(DI / 256, NCH, BATCH);
        scan_passA<<<gridA, 256>>>(xconv, delta, xdbl, A_log, chA, chH);
        scan_passB<<<(BATCH * DI + 255) / 256, 256>>>(chA, chH, hInit);
        scan_passC<<<gridA, 256>>>(xconv, delta, xdbl, A_log, Dv, xz,
                                   hInit, yg);
    }

    // 6) out = yg @ W_out^T       (M=4096, N=1024, K=2048)
    launch_hgemm(yg, DI, W_out, nullptr, out, DM, MTOT, DM, DI, 0);
}

// round 4
// speedup vs baseline: 2.4414x; 1.2832x over previous
#include <cuda_runtime.h>
#include <cuda_bf16.h>
#include <cstdint>
#include <math.h>

// ---------------------------------------------------------------------------
// SelectiveSSM (Mamba-style block) — split-bf16 HMMA GEMMs, cp.async pipeline
//   B=2, L=2048, d_model=1024, d_inner=2048, d_state=16, d_conv=4
// Operands pre-split to bf16 hi/lo in GMEM (once), GEMM streams bf16 via
// cp.async into 3-stage swizzled SMEM, mma.sync.m16n8k16 with 3-term split
// (hi*hi + hi*lo + lo*hi; dropped lo*lo ~ 2^-18).
// ---------------------------------------------------------------------------

#define BATCH  2
#define SEQ    2048
#define DM     1024
#define DI     2048
#define DS     16
#define DC     4
#define DXL    (DI + 2*DS)      // 2080
#define CHUNK  128
#define NCH    (SEQ / CHUNK)    // 16
#define MTOT   (BATCH * SEQ)    // 4096

typedef __nv_bfloat16  bf16;
typedef __nv_bfloat162 bf162;

// ------------------------- scratch (static, no mallocs) -------------------
__device__ float g_xz   [(size_t)MTOT * 2 * DI];
__device__ float g_xconv[(size_t)MTOT * DI];
__device__ float g_xdbl [(size_t)MTOT * DXL];
__device__ float g_delta[(size_t)MTOT * DI];
__device__ float g_chA  [(size_t)BATCH * NCH * DI * DS];
__device__ float g_chH  [(size_t)BATCH * NCH * DI * DS];
__device__ float g_hInit[(size_t)BATCH * NCH * DI * DS];

// bf16 hi/lo operand buffers
__device__ __align__(16) bf16 g_x_hi   [(size_t)MTOT * DM];
__device__ __align__(16) bf16 g_x_lo   [(size_t)MTOT * DM];
__device__ __align__(16) bf16 g_Win_hi [(size_t)(2*DI) * DM];
__device__ __align__(16) bf16 g_Win_lo [(size_t)(2*DI) * DM];
__device__ __align__(16) bf16 g_Wx_hi  [(size_t)DXL * DI];
__device__ __align__(16) bf16 g_Wx_lo  [(size_t)DXL * DI];
__device__ __align__(16) bf16 g_Wdt_hi [(size_t)DI * DI];
__device__ __align__(16) bf16 g_Wdt_lo [(size_t)DI * DI];
__device__ __align__(16) bf16 g_Wout_hi[(size_t)DM * DI];
__device__ __align__(16) bf16 g_Wout_lo[(size_t)DM * DI];
__device__ __align__(16) bf16 g_xc_hi  [(size_t)MTOT * DI];
__device__ __align__(16) bf16 g_xc_lo  [(size_t)MTOT * DI];
__device__ __align__(16) bf16 g_xd_hi  [(size_t)MTOT * DXL];
__device__ __align__(16) bf16 g_xd_lo  [(size_t)MTOT * DXL];
__device__ __align__(16) bf16 g_yg_hi  [(size_t)MTOT * DI];
__device__ __align__(16) bf16 g_yg_lo  [(size_t)MTOT * DI];

// ======================= helpers ===========================================
__device__ __forceinline__ uint32_t smem_u32(const void* p) {
    uint32_t a;
    asm("{ .reg .u64 t; cvta.to.shared.u64 t, %1; cvt.u32.u64 %0, t; }"
        : "=r"(a) : "l"(p));
    return a;
}

__device__ __forceinline__ uint32_t swz(uint32_t off) {     // SW128 swizzle
    return off ^ ((off >> 3) & 0x70);
}

__device__ __forceinline__ void ldsm4(uint32_t* r, uint32_t addr) {
    asm volatile("ldmatrix.sync.aligned.m8n8.x4.shared.b16 {%0,%1,%2,%3}, [%4];"
        : "=r"(r[0]), "=r"(r[1]), "=r"(r[2]), "=r"(r[3]) : "r"(addr));
}

__device__ __forceinline__ void mma16816(float* c, const uint32_t* a,
                                         const uint32_t* b) {
    asm volatile(
        "mma.sync.aligned.m16n8k16.row.col.f32.bf16.bf16.f32 "
        "{%0,%1,%2,%3}, {%4,%5,%6,%7}, {%8,%9}, {%0,%1,%2,%3};"
        : "+f"(c[0]), "+f"(c[1]), "+f"(c[2]), "+f"(c[3])
        : "r"(a[0]), "r"(a[1]), "r"(a[2]), "r"(a[3]),
          "r"(b[0]), "r"(b[1]));
}

__device__ __forceinline__ void cp16(uint32_t dst, const void* src, uint32_t sz) {
    asm volatile("cp.async.cg.shared.global [%0], [%1], 16, %2;"
        :: "r"(dst), "l"(src), "r"(sz) : "memory");
}
#define CP_COMMIT() asm volatile("cp.async.commit_group;" ::: "memory")
#define CP_WAIT2()  asm volatile("cp.async.wait_group 2;" ::: "memory")

__device__ __forceinline__ void split2(float a, float b, bf162& h, bf162& l) {
    bf16 h0 = __float2bfloat16(a);
    bf16 h1 = __float2bfloat16(b);
    h.x = h0; h.y = h1;
    l.x = __float2bfloat16(a - __bfloat162float(h0));
    l.y = __float2bfloat16(b - __bfloat162float(h1));
}

// ---------------------------------------------------------------------------
// split fp32 array -> bf16 hi/lo arrays (vectorized by 4)
// ---------------------------------------------------------------------------
__global__ void split_kernel(const float* __restrict__ src,
                             bf16* __restrict__ hi, bf16* __restrict__ lo,
                             int n4)
{
    int i = blockIdx.x * blockDim.x + threadIdx.x;
    if (i >= n4) return;
    float4 v = ((const float4*)src)[i];
    bf162 h0, h1, l0, l1;
    split2(v.x, v.y, h0, l0);
    split2(v.z, v.w, h1, l1);
    ((bf162*)hi)[i*2]   = h0;  ((bf162*)hi)[i*2+1] = h1;
    ((bf162*)lo)[i*2]   = l0;  ((bf162*)lo)[i*2+1] = l1;
}

// ===========================================================================
// split-bf16 GEMM:  C[M,N] = A[M,K] * W[N,K]^T  (bf16 hi/lo in, fp32 out)
// CTA: 128x128 tile, 8 warps (2x4), warp tile 64x32, K-chunk 64,
// 3-stage cp.async pipeline into SW128-swizzled SMEM.
// MODE 0: plain.  MODE 1: softplus(acc + bias[n]).  MODE 2: plain + write
// bf16 hi/lo copy of C (for chained GEMMs).
// Requires M % 128 == 0, K % 64 == 0, N % 8 == 0, lda/ldw elements 8-aligned.
// ===========================================================================

#define TILE_B   16384            // 128 rows x 128 bytes (64 bf16)
#define STAGE_B  (4 * TILE_B)     // Ahi, Alo, Whi, Wlo
#define NSTG     3
#define GEMM_SMEM (NSTG * STAGE_B)   // 196608

__device__ __forceinline__ void stage_load(
    uint32_t sbase,
    const bf16* __restrict__ Ahi, const bf16* __restrict__ Alo, int lda, int m0,
    const bf16* __restrict__ Whi, const bf16* __restrict__ Wlo, int ldw,
    int n0, int N, int k0, int tid)
{
#pragma unroll
    for (int it = 0; it < 4; it++) {
        const int chunk = tid + it * 256;      // 0..1023
        const int row = chunk >> 3;
        const int c16 = chunk & 7;
        const uint32_t soff = swz((uint32_t)(row * 128 + c16 * 16));
        const size_t aoff = (size_t)(m0 + row) * lda + k0 + c16 * 8;
        cp16(sbase + 0 * TILE_B + soff, Ahi + aoff, 16);
        cp16(sbase + 1 * TILE_B + soff, Alo + aoff, 16);
        const int nr = n0 + row;
        const bool v = nr < N;
        const size_t woff = (size_t)(v ? nr : 0) * ldw + k0 + c16 * 8;
        const uint32_t sz = v ? 16u : 0u;
        cp16(sbase + 2 * TILE_B + soff, Whi + woff, sz);
        cp16(sbase + 3 * TILE_B + soff, Wlo + woff, sz);
    }
}

template<int MODE>
__global__ void __launch_bounds__(256, 1) hgemm_bf(
    const bf16* __restrict__ Ahi, const bf16* __restrict__ Alo, int lda,
    const bf16* __restrict__ Whi, const bf16* __restrict__ Wlo,
    const float* __restrict__ bias,
    float* __restrict__ C, int ldc,
    bf16* __restrict__ Chi, bf16* __restrict__ Clo,
    int M, int N, int K)
{
    extern __shared__ __align__(1024) char smem[];
    const uint32_t sb  = smem_u32(smem);
    const int tid  = threadIdx.x;
    const int wid  = tid >> 5;
    const int lane = tid & 31;
    const int wm   = wid >> 2;       // 0..1  (m)
    const int wn   = wid & 3;        // 0..3  (n)
    const int m0   = blockIdx.y * 128;
    const int n0   = blockIdx.x * 128;

    // per-lane ldmatrix row/k-segment mapping
    const int g     = lane >> 3;
    const int aRow  = (lane & 7) + ((g & 1) << 3);
    const int aKsg  = (g >> 1) << 3;
    const int bRow  = (lane & 7) + ((g >> 1) << 3);
    const int bKsg  = (g & 1) << 3;

    float Cf[4][4][4];
#pragma unroll
    for (int i = 0; i < 4; i++)
#pragma unroll
        for (int j = 0; j < 4; j++)
#pragma unroll
            for (int e = 0; e < 4; e++) Cf[i][j][e] = 0.f;

    const int NC = K >> 6;

    // preload NSTG stages
#pragma unroll
    for (int p = 0; p < NSTG; p++) {
        if (p < NC)
            stage_load(sb + p * STAGE_B, Ahi, Alo, lda, m0,
                       Whi, Wlo, K, n0, N, p << 6, tid);
        CP_COMMIT();
    }

    for (int c = 0; c < NC; c++) {
        CP_WAIT2();
        __syncthreads();

        const uint32_t base = sb + (uint32_t)((c % NSTG) * STAGE_B);
        const uint32_t bAhi = base + 0 * TILE_B;
        const uint32_t bAlo = base + 1 * TILE_B;
        const uint32_t bWhi = base + 2 * TILE_B;
        const uint32_t bWlo = base + 3 * TILE_B;

#pragma unroll
        for (int ks = 0; ks < 4; ks++) {
            uint32_t ahi[4][4], alo[4][4], whi[2][4], wlo[2][4];
#pragma unroll
            for (int fm = 0; fm < 4; fm++) {
                uint32_t off = swz((uint32_t)((wm*64 + fm*16 + aRow) * 128
                                              + (ks*16 + aKsg) * 2));
                ldsm4(ahi[fm], bAhi + off);
                ldsm4(alo[fm], bAlo + off);
            }
#pragma unroll
            for (int h = 0; h < 2; h++) {
                uint32_t off = swz((uint32_t)((wn*32 + h*16 + bRow) * 128
                                              + (ks*16 + bKsg) * 2));
                ldsm4(whi[h], bWhi + off);
                ldsm4(wlo[h], bWlo + off);
            }
#pragma unroll
            for (int fm = 0; fm < 4; fm++) {
#pragma unroll
                for (int fn = 0; fn < 4; fn++) {
                    const uint32_t* bh = &whi[fn >> 1][(fn & 1) * 2];
                    const uint32_t* bl = &wlo[fn >> 1][(fn & 1) * 2];
                    mma16816(Cf[fm][fn], ahi[fm], bh);
                    mma16816(Cf[fm][fn], ahi[fm], bl);
                    mma16816(Cf[fm][fn], alo[fm], bh);
                }
            }
        }
        __syncthreads();

        {
            const int cn = c + NSTG;
            if (cn < NC)
                stage_load(sb + (c % NSTG) * STAGE_B, Ahi, Alo, lda, m0,
                           Whi, Wlo, K, n0, N, cn << 6, tid);
            CP_COMMIT();
        }
    }

    // epilogue
    const int mrow = m0 + wm * 64 + (lane >> 2);
    const int ncol = n0 + wn * 32 + (lane & 3) * 2;
#pragma unroll
    for (int fm = 0; fm < 4; fm++) {
#pragma unroll
        for (int fn = 0; fn < 4; fn++) {
#pragma unroll
            for (int half = 0; half < 2; half++) {
                const int m = mrow + fm * 16 + half * 8;
                const int n = ncol + fn * 8;
                if (n < N) {
                    float v0 = Cf[fm][fn][half * 2 + 0];
                    float v1 = Cf[fm][fn][half * 2 + 1];
                    if (MODE == 1) {
                        v0 += bias[n];
                        v1 += bias[n + 1];
                        v0 = (v0 > 20.f) ? v0 : log1pf(expf(v0));
                        v1 = (v1 > 20.f) ? v1 : log1pf(expf(v1));
                    }
                    *(float2*)&C[(size_t)m * ldc + n] = make_float2(v0, v1);
                    if (MODE == 2) {
                        bf162 h, l;
                        split2(v0, v1, h, l);
                        *(bf162*)&Chi[(size_t)m * ldc + n] = h;
                        *(bf162*)&Clo[(size_t)m * ldc + n] = l;
                    }
                }
            }
        }
    }
}

// ---------------------------------------------------------------------------
// Depthwise causal conv (K=4) over xz[:, :, :DI], then SiLU; outputs fp32 +
// bf16 hi/lo (for the following GEMM).
// ---------------------------------------------------------------------------
__global__ void conv_silu_kernel(const float* __restrict__ xz,
                                 const float* __restrict__ w,
                                 const float* __restrict__ bconv,
                                 float* __restrict__ xconv,
                                 bf16* __restrict__ xchi,
                                 bf16* __restrict__ xclo)
{
    const int idx = blockIdx.x * blockDim.x + threadIdx.x;
    if (idx >= MTOT * DI) return;
    const int d  = idx & (DI - 1);
    const int ml = idx >> 11;
    const int l  = ml & (SEQ - 1);

    float acc = bconv[d];
#pragma unroll
    for (int k = 0; k < DC; k++) {
        const int lt = l - (DC - 1) + k;
        if (lt >= 0)
            acc += xz[(size_t)(ml - (DC - 1) + k) * (2 * DI) + d] * w[d * DC + k];
    }
    const float sg = 1.f / (1.f + expf(-acc));
    const float v = acc * sg;
    xconv[idx] = v;
    bf16 h = __float2bfloat16(v);
    xchi[idx] = h;
    xclo[idx] = __float2bfloat16(v - __bfloat162float(h));
}

// ---------------------------------------------------------------------------
// Scan pass A
// ---------------------------------------------------------------------------
__global__ void __launch_bounds__(256) scan_passA(
    const float* __restrict__ xconv, const float* __restrict__ delta,
    const float* __restrict__ xdbl,  const float* __restrict__ A_log,
    float* __restrict__ chA, float* __restrict__ chH)
{
    __shared__ float Bsm[CHUNK][DS];
    const int d = blockIdx.x * blockDim.x + threadIdx.x;
    const int c = blockIdx.y, b = blockIdx.z;

    for (int i = threadIdx.x; i < CHUNK * DS; i += blockDim.x) {
        const int t = i >> 4, s = i & 15;
        Bsm[t][s] = xdbl[(size_t)(b * SEQ + c * CHUNK + t) * DXL + DI + s];
    }
    __syncthreads();

    float Aa[DS], st[DS], cum[DS];
#pragma unroll
    for (int s = 0; s < DS; s++) {
        Aa[s]  = -expf(A_log[d * DS + s]);
        st[s]  = 0.f;
        cum[s] = 1.f;
    }
    const size_t base = (size_t)(b * SEQ + c * CHUNK) * DI + d;
    for (int t = 0; t < CHUNK; t++) {
        const float dt = delta[base + (size_t)t * DI];
        const float xv = xconv[base + (size_t)t * DI];
#pragma unroll
        for (int s = 0; s < DS; s++) {
            const float dec = __expf(dt * Aa[s]);
            cum[s] *= dec;
            st[s]   = dec * st[s] + Bsm[t][s] * xv;
        }
    }
    const size_t o = ((size_t)(b * NCH + c) * DI + d) * DS;
#pragma unroll
    for (int s = 0; s < DS; s++) { chA[o + s] = cum[s]; chH[o + s] = st[s]; }
}

// ---------------------------------------------------------------------------
// Scan pass B
// ---------------------------------------------------------------------------
__global__ void scan_passB(const float* __restrict__ chA,
                           const float* __restrict__ chH,
                           float* __restrict__ hInit)
{
    const int idx = blockIdx.x * blockDim.x + threadIdx.x;
    if (idx >= BATCH * DI) return;
    const int b = idx / DI, d = idx % DI;
    float h[DS];
#pragma unroll
    for (int s = 0; s < DS; s++) h[s] = 0.f;
    for (int c = 0; c < NCH; c++) {
        const size_t o = ((size_t)(b * NCH + c) * DI + d) * DS;
#pragma unroll
        for (int s = 0; s < DS; s++) hInit[o + s] = h[s];
#pragma unroll
        for (int s = 0; s < DS; s++) h[s] = chA[o + s] * h[s] + chH[o + s];
    }
}

// ---------------------------------------------------------------------------
// Scan pass C: replay + C-contraction + D-skip + y*silu(z); writes yg hi/lo.
// ---------------------------------------------------------------------------
__global__ void __launch_bounds__(256) scan_passC(
    const float* __restrict__ xconv, const float* __restrict__ delta,
    const float* __restrict__ xdbl,  const float* __restrict__ A_log,
    const float* __restrict__ Dv,    const float* __restrict__ xz,
    const float* __restrict__ hInit,
    bf16* __restrict__ yghi, bf16* __restrict__ yglo)
{
    __shared__ float Bsm[CHUNK][DS];
    __shared__ float Csm[CHUNK][DS];
    const int d = blockIdx.x * blockDim.x + threadIdx.x;
    const int c = blockIdx.y, b = blockIdx.z;

    for (int i = threadIdx.x; i < CHUNK * DS; i += blockDim.x) {
        const int t = i >> 4, s = i & 15;
        const size_t row = (size_t)(b * SEQ + c * CHUNK + t) * DXL;
        Bsm[t][s] = xdbl[row + DI + s];
        Csm[t][s] = xdbl[row + DI + DS + s];
    }
    __syncthreads();

    float Aa[DS], st[DS];
    const size_t o = ((size_t)(b * NCH + c) * DI + d) * DS;
#pragma unroll
    for (int s = 0; s < DS; s++) {
        Aa[s] = -expf(A_log[d * DS + s]);
        st[s] = hInit[o + s];
    }
    const float Dd = Dv[d];
    const size_t base = (size_t)(b * SEQ + c * CHUNK) * DI + d;
    for (int t = 0; t < CHUNK; t++) {
        const float dt = delta[base + (size_t)t * DI];
        const float xv = xconv[base + (size_t)t * DI];
        float y = 0.f;
#pragma unroll
        for (int s = 0; s < DS; s++) {
            const float dec = __expf(dt * Aa[s]);
            st[s] = dec * st[s] + Bsm[t][s] * xv;
            y += st[s] * Csm[t][s];
        }
        y += Dd * xv;
        const float z = xz[(size_t)(b * SEQ + c * CHUNK + t) * (2 * DI) + DI + d];
        const float sg = 1.f / (1.f + expf(-z));
        const float v = y * (z * sg);
        const size_t oi = base + (size_t)t * DI;
        bf16 h = __float2bfloat16(v);
        yghi[oi] = h;
        yglo[oi] = __float2bfloat16(v - __bfloat162float(h));
    }
}

// ---------------------------------------------------------------------------
static void launch_split(const float* src, bf16* hi, bf16* lo, size_t n)
{
    int n4 = (int)(n / 4);
    split_kernel<<<(n4 + 255) / 256, 256>>>(src, hi, lo, n4);
}

template<int MODE>
static void launch_hgemm(const bf16* Ahi, const bf16* Alo, int lda,
                         const bf16* Whi, const bf16* Wlo,
                         const float* bias, float* C, int ldc,
                         bf16* Chi, bf16* Clo, int M, int N, int K)
{
    dim3 grid((N + 127) / 128, M / 128);
    cudaFuncSetAttribute(hgemm_bf<MODE>,
        cudaFuncAttributeMaxDynamicSharedMemorySize, GEMM_SMEM);
    hgemm_bf<MODE><<<grid, 256, GEMM_SMEM>>>(Ahi, Alo, lda, Whi, Wlo,
                                             bias, C, ldc, Chi, Clo, M, N, K);
}

extern "C" void kernel_launch(void* const* d_in, const int* in_sizes, int n_in,
                              void* d_out, int out_size)
{
    const float* x      = (const float*)d_in[0];
    const float* W_in   = (const float*)d_in[1];
    const float* w_conv = (const float*)d_in[2];
    const float* b_conv = (const float*)d_in[3];
    const float* W_x    = (const float*)d_in[4];
    const float* W_dt   = (const float*)d_in[5];
    const float* b_dt   = (const float*)d_in[6];
    const float* A_log  = (const float*)d_in[7];
    const float* Dv     = (const float*)d_in[8];
    const float* W_out  = (const float*)d_in[9];
    float* out = (float*)d_out;

    float *xz, *xconv, *xdbl, *delta, *chA, *chH, *hInit;
    cudaGetSymbolAddress((void**)&xz,    g_xz);
    cudaGetSymbolAddress((void**)&xconv, g_xconv);
    cudaGetSymbolAddress((void**)&xdbl,  g_xdbl);
    cudaGetSymbolAddress((void**)&delta, g_delta);
    cudaGetSymbolAddress((void**)&chA,   g_chA);
    cudaGetSymbolAddress((void**)&chH,   g_chH);
    cudaGetSymbolAddress((void**)&hInit, g_hInit);

    bf16 *x_hi, *x_lo, *Win_hi, *Win_lo, *Wx_hi, *Wx_lo, *Wdt_hi, *Wdt_lo,
         *Wout_hi, *Wout_lo, *xc_hi, *xc_lo, *xd_hi, *xd_lo, *yg_hi, *yg_lo;
    cudaGetSymbolAddress((void**)&x_hi,    g_x_hi);
    cudaGetSymbolAddress((void**)&x_lo,    g_x_lo);
    cudaGetSymbolAddress((void**)&Win_hi,  g_Win_hi);
    cudaGetSymbolAddress((void**)&Win_lo,  g_Win_lo);
    cudaGetSymbolAddress((void**)&Wx_hi,   g_Wx_hi);
    cudaGetSymbolAddress((void**)&Wx_lo,   g_Wx_lo);
    cudaGetSymbolAddress((void**)&Wdt_hi,  g_Wdt_hi);
    cudaGetSymbolAddress((void**)&Wdt_lo,  g_Wdt_lo);
    cudaGetSymbolAddress((void**)&Wout_hi, g_Wout_hi);
    cudaGetSymbolAddress((void**)&Wout_lo, g_Wout_lo);
    cudaGetSymbolAddress((void**)&xc_hi,   g_xc_hi);
    cudaGetSymbolAddress((void**)&xc_lo,   g_xc_lo);
    cudaGetSymbolAddress((void**)&xd_hi,   g_xd_hi);
    cudaGetSymbolAddress((void**)&xd_lo,   g_xd_lo);
    cudaGetSymbolAddress((void**)&yg_hi,   g_yg_hi);
    cudaGetSymbolAddress((void**)&yg_lo,   g_yg_lo);

    // 0) split inputs/weights to bf16 hi/lo
    launch_split(x,     x_hi,    x_lo,    (size_t)MTOT * DM);
    launch_split(W_in,  Win_hi,  Win_lo,  (size_t)(2*DI) * DM);
    launch_split(W_x,   Wx_hi,   Wx_lo,   (size_t)DXL * DI);
    launch_split(W_dt,  Wdt_hi,  Wdt_lo,  (size_t)DI * DI);
    launch_split(W_out, Wout_hi, Wout_lo, (size_t)DM * DI);

    // 1) xz = x @ W_in^T          (M=4096, N=4096, K=1024)
    launch_hgemm<0>(x_hi, x_lo, DM, Win_hi, Win_lo, nullptr,
                    xz, 2 * DI, nullptr, nullptr, MTOT, 2 * DI, DM);

    // 2) depthwise causal conv + silu (fp32 + hi/lo outputs)
    {
        int n = MTOT * DI;
        conv_silu_kernel<<<(n + 255) / 256, 256>>>(xz, w_conv, b_conv,
                                                   xconv, xc_hi, xc_lo);
    }

    // 3) xdbl = xconv @ W_x^T     (M=4096, N=2080, K=2048); fp32 + hi/lo out
    launch_hgemm<2>(xc_hi, xc_lo, DI, Wx_hi, Wx_lo, nullptr,
                    xdbl, DXL, xd_hi, xd_lo, MTOT, DXL, DI);

    // 4) delta = softplus(xdbl[:, :DI] @ W_dt^T + b_dt)   (A lda = DXL)
    launch_hgemm<1>(xd_hi, xd_lo, DXL, Wdt_hi, Wdt_lo, b_dt,
                    delta, DI, nullptr, nullptr, MTOT, DI, DI);

    // 5) chunked selective scan
    {
        dim3 gridA(DI / 256, NCH, BATCH);
        scan_passA<<<gridA, 256>>>(xconv, delta, xdbl, A_log, chA, chH);
        scan_passB<<<(BATCH * DI + 255) / 256, 256>>>(chA, chH, hInit);
        scan_passC<<<gridA, 256>>>(xconv, delta, xdbl, A_log, Dv, xz,
                                   hInit, yg_hi, yg_lo);
    }

    // 6) out = yg @ W_out^T       (M=4096, N=1024, K=2048)
    launch_hgemm<0>(yg_hi, yg_lo, DI, Wout_hi, Wout_lo, nullptr,
                    out, DM, nullptr, nullptr, MTOT, DM, DI);
}